// round 1
// baseline (speedup 1.0000x reference)
#include <cuda_runtime.h>
#include <math.h>

#define Bdim 2
#define Lq 8192
#define Edim 1024
#define Hn 16
#define Dh 64
#define Cch 256
#define Nch (Lq / Cch)            // 32
#define BL (Bdim * Lq)            // 16384
#define NCHUNKS (Bdim * Hn * Nch) // 1024

// ---------------- scratch (device globals: no allocation allowed) ----------
__device__ float g_q[BL * Edim];
__device__ float g_k[BL * Edim];
__device__ float g_v[BL * Edim];
__device__ float g_attn[BL * Edim];
__device__ float g_y[BL * Edim];
__device__ float g_Sc[NCHUNKS * Dh * Dh];
__device__ float g_Sp[NCHUNKS * Dh * Dh];
__device__ float g_zc[NCHUNKS * Dh];
__device__ float g_zp[NCHUNKS * Dh];

// ---------------- GEMM: C = act(A @ W + bias [+ resid]) --------------------
// ACT: 0 = none, 1 = phi (elu+1), 2 = add residual
// OSEL: 0->g_q 1->g_k 2->g_v 3->g_y ; ISEL: 0->Aext, 1->g_attn
template <int ACT, int OSEL, int ISEL>
__global__ void __launch_bounds__(256) gemm_kernel(
    const float* __restrict__ Aext, const float* __restrict__ W,
    const float* __restrict__ bias, const float* __restrict__ resid)
{
    const int N = Edim, K = Edim;
    const int BK = 8;
    __shared__ float As[2][BK][128];
    __shared__ float Bs[2][BK][128];

    const float* A = (ISEL == 0) ? Aext : &g_attn[0];
    float* Cout = (OSEL == 0) ? &g_q[0] : (OSEL == 1) ? &g_k[0]
                : (OSEL == 2) ? &g_v[0] : &g_y[0];

    int tid = threadIdx.x;
    int bm = blockIdx.y * 128;
    int bn = blockIdx.x * 128;

    int arow = tid >> 1, acol = (tid & 1) * 4;
    int brow = tid >> 5, bcol = (tid & 31) * 4;
    const float* Ap = A + (size_t)(bm + arow) * K + acol;
    const float* Wp = W + (size_t)brow * N + bn + bcol;

    float4 aR = *(const float4*)Ap;
    float4 bR = *(const float4*)Wp;
    As[0][acol + 0][arow] = aR.x;
    As[0][acol + 1][arow] = aR.y;
    As[0][acol + 2][arow] = aR.z;
    As[0][acol + 3][arow] = aR.w;
    *(float4*)&Bs[0][brow][bcol] = bR;
    __syncthreads();

    float acc[8][8];
#pragma unroll
    for (int i = 0; i < 8; i++)
#pragma unroll
        for (int j = 0; j < 8; j++) acc[i][j] = 0.f;

    int tr = (tid >> 4) * 8;
    int tc = (tid & 15) * 8;

    const int nt = K / BK;
    for (int kt = 0; kt < nt; kt++) {
        int cur = kt & 1;
        if (kt + 1 < nt) {
            aR = *(const float4*)(Ap + (kt + 1) * BK);
            bR = *(const float4*)(Wp + (size_t)(kt + 1) * BK * N);
        }
#pragma unroll
        for (int kk = 0; kk < BK; kk++) {
            float4 a0 = *(const float4*)&As[cur][kk][tr];
            float4 a1 = *(const float4*)&As[cur][kk][tr + 4];
            float4 b0 = *(const float4*)&Bs[cur][kk][tc];
            float4 b1 = *(const float4*)&Bs[cur][kk][tc + 4];
            float av[8] = {a0.x, a0.y, a0.z, a0.w, a1.x, a1.y, a1.z, a1.w};
            float bv[8] = {b0.x, b0.y, b0.z, b0.w, b1.x, b1.y, b1.z, b1.w};
#pragma unroll
            for (int i = 0; i < 8; i++)
#pragma unroll
                for (int j = 0; j < 8; j++) acc[i][j] += av[i] * bv[j];
        }
        if (kt + 1 < nt) {
            int nx = cur ^ 1;
            As[nx][acol + 0][arow] = aR.x;
            As[nx][acol + 1][arow] = aR.y;
            As[nx][acol + 2][arow] = aR.z;
            As[nx][acol + 3][arow] = aR.w;
            *(float4*)&Bs[nx][brow][bcol] = bR;
            __syncthreads();
        }
    }

#pragma unroll
    for (int i = 0; i < 8; i++) {
        int row = bm + tr + i;
#pragma unroll
        for (int j = 0; j < 8; j += 4) {
            int col = bn + tc + j;
            float4 r;
            r.x = acc[i][j + 0] + bias[col + 0];
            r.y = acc[i][j + 1] + bias[col + 1];
            r.z = acc[i][j + 2] + bias[col + 2];
            r.w = acc[i][j + 3] + bias[col + 3];
            if (ACT == 1) {  // phi = elu(x)+1 : x>0 ? x+1 : exp(x)
                r.x = r.x > 0.f ? r.x + 1.f : expf(r.x);
                r.y = r.y > 0.f ? r.y + 1.f : expf(r.y);
                r.z = r.z > 0.f ? r.z + 1.f : expf(r.z);
                r.w = r.w > 0.f ? r.w + 1.f : expf(r.w);
            }
            if (ACT == 2) {
                float4 xr = *(const float4*)&resid[(size_t)row * N + col];
                r.x += xr.x; r.y += xr.y; r.z += xr.z; r.w += xr.w;
            }
            *(float4*)&Cout[(size_t)row * N + col] = r;
        }
    }
}

// ---------------- per-chunk KV stats: S_c = k^T v, z_c = sum k --------------
__global__ void __launch_bounds__(256) chunk_stats_kernel()
{
    __shared__ float ks[64][64];
    __shared__ float vs[64][64];
    int blk = blockIdx.x;
    int n = blk % Nch;
    int h = (blk / Nch) % Hn;
    int b = blk / (Nch * Hn);
    int rowbase = b * Lq + n * Cch;
    int colbase = h * Dh;
    int t = threadIdx.x;
    int d = t >> 2;
    int e0 = (t & 3) * 16;

    float acc[16];
#pragma unroll
    for (int j = 0; j < 16; j++) acc[j] = 0.f;
    float zacc = 0.f;

    for (int st = 0; st < Cch; st += 64) {
        for (int i = t; i < 1024; i += 256) {
            int r = i >> 4, c4 = (i & 15) * 4;
            size_t gofs = (size_t)(rowbase + st + r) * Edim + colbase + c4;
            *(float4*)&ks[r][c4] = *(const float4*)&g_k[gofs];
            *(float4*)&vs[r][c4] = *(const float4*)&g_v[gofs];
        }
        __syncthreads();
        for (int s = 0; s < 64; s++) {
            float kd = ks[s][d];
            const float4* v4 = (const float4*)&vs[s][e0];
#pragma unroll
            for (int j = 0; j < 4; j++) {
                float4 vv = v4[j];
                acc[4 * j + 0] += kd * vv.x;
                acc[4 * j + 1] += kd * vv.y;
                acc[4 * j + 2] += kd * vv.z;
                acc[4 * j + 3] += kd * vv.w;
            }
            zacc += kd;
        }
        __syncthreads();
    }

    float* Sb = &g_Sc[(size_t)blk * (Dh * Dh) + d * 64 + e0];
#pragma unroll
    for (int j = 0; j < 4; j++) {
        float4 o;
        o.x = acc[4 * j + 0]; o.y = acc[4 * j + 1];
        o.z = acc[4 * j + 2]; o.w = acc[4 * j + 3];
        *(float4*)(Sb + 4 * j) = o;
    }
    if ((t & 3) == 0) g_zc[blk * Dh + d] = zacc;
}

// ---------------- exclusive prefix scan over chunks per (b,h) ---------------
__global__ void __launch_bounds__(256) scan_kernel()
{
    int bh = blockIdx.x;  // 0..B*H-1
    int t = threadIdx.x;
    float run[16];
#pragma unroll
    for (int i = 0; i < 16; i++) run[i] = 0.f;
    float zrun = 0.f;

    for (int n = 0; n < Nch; n++) {
        size_t base = ((size_t)bh * Nch + n) * (Dh * Dh);
#pragma unroll
        for (int i = 0; i < 16; i++) {
            int idx = t + i * 256;
            g_Sp[base + idx] = run[i];
            run[i] += g_Sc[base + idx];
        }
        if (t < Dh) {
            size_t zb = ((size_t)bh * Nch + n) * Dh + t;
            g_zp[zb] = zrun;
            zrun += g_zc[zb];
        }
    }
}

// ---------------- per-chunk attention output --------------------------------
__global__ void __launch_bounds__(256, 1) chunk_out_kernel()
{
    __shared__ float ks[64][64];
    __shared__ float vs[64][64];
    int blk = blockIdx.x;
    int n = blk % Nch;
    int h = (blk / Nch) % Hn;
    int b = blk / (Nch * Hn);
    int rowbase = b * Lq + n * Cch;
    int colbase = h * Dh;
    int t = threadIdx.x;  // row within chunk (0..255)

    const float* qrow = &g_q[(size_t)(rowbase + t) * Edim + colbase];

    float qv[64];
#pragma unroll
    for (int j = 0; j < 16; j++) {
        float4 qq = *(const float4*)(qrow + 4 * j);
        qv[4 * j + 0] = qq.x; qv[4 * j + 1] = qq.y;
        qv[4 * j + 2] = qq.z; qv[4 * j + 3] = qq.w;
    }

    float acc[64];
#pragma unroll
    for (int j = 0; j < 64; j++) acc[j] = 0.f;

    // q @ S_prefix (q re-read via __ldg so the dynamic index stays off registers)
    const float* Sb = &g_Sp[(size_t)blk * (Dh * Dh)];
    for (int d = 0; d < 64; d++) {
        float qd = __ldg(qrow + d);
        const float4* S4 = (const float4*)(Sb + d * 64);
#pragma unroll
        for (int j = 0; j < 16; j++) {
            float4 sv = __ldg(S4 + j);
            acc[4 * j + 0] += qd * sv.x;
            acc[4 * j + 1] += qd * sv.y;
            acc[4 * j + 2] += qd * sv.z;
            acc[4 * j + 3] += qd * sv.w;
        }
    }

    // den = q . z_prefix
    float den = 0.f;
    const float* zb = &g_zp[(size_t)blk * Dh];
#pragma unroll
    for (int j = 0; j < 16; j++) {
        den += qv[4 * j + 0] * __ldg(zb + 4 * j + 0);
        den += qv[4 * j + 1] * __ldg(zb + 4 * j + 1);
        den += qv[4 * j + 2] * __ldg(zb + 4 * j + 2);
        den += qv[4 * j + 3] * __ldg(zb + 4 * j + 3);
    }

    // intra-chunk causal part, tiled over s in blocks of 64
    for (int st = 0; st < Cch; st += 64) {
        for (int i = t; i < 1024; i += 256) {
            int r = i >> 4, c4 = (i & 15) * 4;
            size_t gofs = (size_t)(rowbase + st + r) * Edim + colbase + c4;
            *(float4*)&ks[r][c4] = *(const float4*)&g_k[gofs];
            *(float4*)&vs[r][c4] = *(const float4*)&g_v[gofs];
        }
        __syncthreads();
        int smax = t - st + 1;
        if (smax > 64) smax = 64;
        for (int s = 0; s < smax; s++) {
            const float4* k4 = (const float4*)&ks[s][0];
            float dot = 0.f;
#pragma unroll
            for (int j = 0; j < 16; j++) {
                float4 kk = k4[j];
                dot += qv[4 * j + 0] * kk.x + qv[4 * j + 1] * kk.y
                     + qv[4 * j + 2] * kk.z + qv[4 * j + 3] * kk.w;
            }
            den += dot;
            const float4* v4 = (const float4*)&vs[s][0];
#pragma unroll
            for (int j = 0; j < 16; j++) {
                float4 vv = v4[j];
                acc[4 * j + 0] += dot * vv.x;
                acc[4 * j + 1] += dot * vv.y;
                acc[4 * j + 2] += dot * vv.z;
                acc[4 * j + 3] += dot * vv.w;
            }
        }
        __syncthreads();
    }

    float inv = 1.0f / (den + 1e-6f);
    float* orow = &g_attn[(size_t)(rowbase + t) * Edim + colbase];
#pragma unroll
    for (int j = 0; j < 16; j++) {
        float4 o;
        o.x = acc[4 * j + 0] * inv;
        o.y = acc[4 * j + 1] * inv;
        o.z = acc[4 * j + 2] * inv;
        o.w = acc[4 * j + 3] * inv;
        *(float4*)(orow + 4 * j) = o;
    }
}

// ---------------- LayerNorm --------------------------------------------------
__global__ void __launch_bounds__(256) ln_kernel(
    const float* __restrict__ gamma, const float* __restrict__ beta,
    float* __restrict__ out)
{
    int row = blockIdx.x;
    int t = threadIdx.x;
    const float* yr = &g_y[(size_t)row * Edim];
    float4 v = *(const float4*)(yr + t * 4);
    float s = v.x + v.y + v.z + v.w;
    float ss = v.x * v.x + v.y * v.y + v.z * v.z + v.w * v.w;
#pragma unroll
    for (int o = 16; o; o >>= 1) {
        s += __shfl_down_sync(0xffffffffu, s, o);
        ss += __shfl_down_sync(0xffffffffu, ss, o);
    }
    __shared__ float sh_s[8], sh_ss[8];
    int w = t >> 5, ln = t & 31;
    if (ln == 0) { sh_s[w] = s; sh_ss[w] = ss; }
    __syncthreads();
    if (t == 0) {
        float a = 0.f, b2 = 0.f;
#pragma unroll
        for (int i = 0; i < 8; i++) { a += sh_s[i]; b2 += sh_ss[i]; }
        sh_s[0] = a; sh_ss[0] = b2;
    }
    __syncthreads();
    float mu = sh_s[0] * (1.0f / Edim);
    float var = sh_ss[0] * (1.0f / Edim) - mu * mu;
    float rstd = rsqrtf(var + 1e-5f);
    float4 g = *(const float4*)(gamma + t * 4);
    float4 bb = *(const float4*)(beta + t * 4);
    float4 o;
    o.x = g.x * (v.x - mu) * rstd + bb.x;
    o.y = g.y * (v.y - mu) * rstd + bb.y;
    o.z = g.z * (v.z - mu) * rstd + bb.z;
    o.w = g.w * (v.w - mu) * rstd + bb.w;
    *(float4*)(out + (size_t)row * Edim + t * 4) = o;
}

// ---------------- launch ------------------------------------------------------
extern "C" void kernel_launch(void* const* d_in, const int* in_sizes, int n_in,
                              void* d_out, int out_size)
{
    const float* x     = (const float*)d_in[0];
    const float* Wq    = (const float*)d_in[1];
    const float* bq    = (const float*)d_in[2];
    const float* Wk    = (const float*)d_in[3];
    const float* bk    = (const float*)d_in[4];
    const float* Wv    = (const float*)d_in[5];
    const float* bv    = (const float*)d_in[6];
    const float* Wo    = (const float*)d_in[7];
    const float* bo    = (const float*)d_in[8];
    const float* gamma = (const float*)d_in[9];
    const float* beta  = (const float*)d_in[10];
    float* out = (float*)d_out;

    dim3 ggrid(Edim / 128, BL / 128);

    gemm_kernel<1, 0, 0><<<ggrid, 256>>>(x, Wq, bq, nullptr);   // q = phi(x@Wq+bq)
    gemm_kernel<1, 1, 0><<<ggrid, 256>>>(x, Wk, bk, nullptr);   // k = phi(x@Wk+bk)
    gemm_kernel<0, 2, 0><<<ggrid, 256>>>(x, Wv, bv, nullptr);   // v = x@Wv+bv
    chunk_stats_kernel<<<NCHUNKS, 256>>>();
    scan_kernel<<<Bdim * Hn, 256>>>();
    chunk_out_kernel<<<NCHUNKS, 256>>>();
    gemm_kernel<2, 3, 1><<<ggrid, 256>>>(nullptr, Wo, bo, x);   // y = attn@Wo+bo+x
    ln_kernel<<<BL, 256>>>(gamma, beta, out);
}